// round 11
// baseline (speedup 1.0000x reference)
#include <cuda_runtime.h>
#include <cuda_bf16.h>
#include <cstdint>

// Problem dims
#define NV 64
#define NT 8192
#define NDA 256
#define NDS 256
#define NKR 8
#define NDU 64
#define NKA 40
#define M_TOTAL (NV * NT)  // 524288

// Output layout (float32, tuple flattened in reference-return order)
#define OFF_PDET 0
#define OFF_TAUX 1
#define OFF_YHAT 2
#define OFF_E    42
#define OFF_EV   (OFF_E + M_TOTAL)
#define OFF_RV   (OFF_EV + NV)
#define OFF_IV   (OFF_RV + NV)
#define OFF_ST   (OFF_IV + NV)
#define OFF_EN   (OFF_ST + M_TOTAL)
#define OFF_FLAG (OFF_EN + M_TOTAL)

// GEMM tiling: CTA = 64 rows x 256 cols, k-steps of 16
#define BM 64
#define NKT 16                       // 256 / 16
#define GEMM_BLOCKS (M_TOTAL / BM)   // 8192
#define ASTRIDE 258                  // padded bf16 row stride (conflict-free)

// -------- device scratch --------
// B fragments: [kt(16)][term(2: hi,lo)][ntile(32)][lane(32)] as uint2
__device__ uint2  g_Bf[NKT * 2 * 32 * 32];
__device__ float  g_zsn[NDS];
__device__ float  g_rview[NV];
__device__ double g_part[GEMM_BLOCKS];

// -------- helpers --------
__device__ __forceinline__ uint32_t smem_u32(const void* p) {
    return (uint32_t)__cvta_generic_to_shared(p);
}
__device__ __forceinline__ uint32_t pack_bf2(float a, float b) {
    __nv_bfloat162 h = __floats2bfloat162_rn(a, b);
    return *reinterpret_cast<uint32_t*>(&h);
}
__device__ __forceinline__ void cp16(uint32_t saddr, const void* gaddr) {
    asm volatile("cp.async.cg.shared.global [%0], [%1], 16;" :: "r"(saddr), "l"(gaddr));
}
#define CP_COMMIT() asm volatile("cp.async.commit_group;")

#define MMA_BF16(cr, a, bx, by) \
    asm volatile( \
        "mma.sync.aligned.m16n8k16.row.col.f32.bf16.bf16.f32 " \
        "{%0,%1,%2,%3},{%4,%5,%6,%7},{%8,%9},{%0,%1,%2,%3};" \
        : "+f"((cr)[0]), "+f"((cr)[1]), "+f"((cr)[2]), "+f"((cr)[3]) \
        : "r"((a)[0]), "r"((a)[1]), "r"((a)[2]), "r"((a)[3]), "r"(bx), "r"(by))

// ============================================================
// Kernel P: build bf16 hi/lo B fragments in mma.sync per-lane layout
//   B[n][k] = Wwin[n*256 + k]; frag (kt, nt, lane):
//   n = nt*8 + lane/4, k0 = kt*16 + (lane%4)*2
//   reg.x = {B[k0], B[k0+1]}, reg.y = {B[k0+8], B[k0+9]}
// ============================================================
__global__ void k_prep_b(const float* __restrict__ W) {
    int t = blockIdx.x * 256 + threadIdx.x;   // 16384 total
    int kt = t >> 10, nt = (t >> 5) & 31, lane = t & 31;
    int n  = nt * 8 + (lane >> 2);
    int k0 = kt * 16 + (lane & 3) * 2;
    const float* row = W + n * NDA;
    float v0 = row[k0], v1 = row[k0 + 1], v2 = row[k0 + 8], v3 = row[k0 + 9];
    __nv_bfloat16 h0 = __float2bfloat16_rn(v0), h1 = __float2bfloat16_rn(v1);
    __nv_bfloat16 h2 = __float2bfloat16_rn(v2), h3 = __float2bfloat16_rn(v3);
    uint2 hv, lv;
    hv.x = ((uint32_t)__bfloat16_as_ushort(h1) << 16) | __bfloat16_as_ushort(h0);
    hv.y = ((uint32_t)__bfloat16_as_ushort(h3) << 16) | __bfloat16_as_ushort(h2);
    lv.x = pack_bf2(v0 - __bfloat162float(h0), v1 - __bfloat162float(h1));
    lv.y = pack_bf2(v2 - __bfloat162float(h2), v3 - __bfloat162float(h3));
    g_Bf[((kt * 2 + 0) * 32 + nt) * 32 + lane] = hv;
    g_Bf[((kt * 2 + 1) * 32 + nt) * 32 + lane] = lv;
}

// ============================================================
// Kernel A: scalars — zs, s, tau_x, p_det, y_hat, r_view, zsn
// ============================================================
__global__ void k_scalars(const float* __restrict__ alpha, const float* __restrict__ pi,
                          const float* __restrict__ US,
                          const float* __restrict__ Ws_w, const float* __restrict__ Ws_b,
                          const float* __restrict__ det_w, const float* __restrict__ det_b,
                          const float* __restrict__ cls_w, const float* __restrict__ cls_b,
                          const float* __restrict__ tau_c0, const float* __restrict__ lamU,
                          const float* __restrict__ lamC, const float* __restrict__ lamP,
                          const float* __restrict__ lamPi, const float* __restrict__ nu,
                          const float* __restrict__ risk, float* __restrict__ out) {
    __shared__ float us[NKR * NDU];
    __shared__ float zs[NDS];
    __shared__ float red[256];
    int t = threadIdx.x;
    us[t] = US[t];
    us[t + 256] = US[t + 256];
    __syncthreads();

    float z = Ws_b[t];
#pragma unroll 4
    for (int k = 0; k < NKR * NDU; k++) z += Ws_w[t * (NKR * NDU) + k] * us[k];
    zs[t] = z;
    __syncthreads();

    red[t] = z * z;
    __syncthreads();
    for (int s = 128; s > 0; s >>= 1) { if (t < s) red[t] += red[t + s]; __syncthreads(); }
    float ss = red[0];
    __syncthreads();

    red[t] = z * det_w[t];
    __syncthreads();
    for (int s = 128; s > 0; s >>= 1) { if (t < s) red[t] += red[t + s]; __syncthreads(); }
    float sdet = red[0] + det_b[0];
    __syncthreads();

    float norm = fmaxf(sqrtf(ss), 1e-12f);
    g_zsn[t] = zs[t] / norm;

    if (t < NKA) {
        float y = cls_b[t];
#pragma unroll 4
        for (int j = 0; j < NDS; j++) y += cls_w[t * NDS + j] * zs[j];
        out[OFF_YHAT + t] = 1.0f / (1.0f + expf(-y));
    }
    if (t < NV) {
        float r = -0.5f * alpha[t];
        g_rview[t] = r;
        out[OFF_RV + t] = r;
    }
    if (t == 0) {
        float ha = 0.0f;
        for (int i = 0; i < NV; i++) { float a = alpha[i]; ha += a * logf(a + 1e-8f); }
        float Ca = 1.0f - (-ha) / logf((float)NV);
        float hp = 0.0f;
        for (int i = 0; i < NKR; i++) { float p = pi[i]; hp += p * logf(p + 1e-8f); }
        float up = (-hp) / logf((float)NKR);
        float tx = tau_c0[0] - lamU[0] * nu[0] - lamC[0] * Ca + lamP[0] * risk[0] + lamPi[0] * up;
        out[OFF_TAUX] = tx;
        out[OFF_PDET] = 1.0f / (1.0f + expf(-(sdet - tx)));
    }
}

// ============================================================
// Kernel B: bf16 mma.sync GEMM (3-term hi/lo split) + fused row reduce -> e
//   C[m][n] = sum_k h[m][k] * Wwin[n][k];  e = (C.zsn)/max(||C||,1e-12)
//   8 warps: mbase = (wid&3)*16, nhalf = wid>>2 (128 cols each)
// ============================================================
struct __align__(16) SmemG {
    uint2 Bs[2][2 * 32 * 32];          // 32 KB (double-buffered B frag stage)
    __nv_bfloat16 Ah[BM * ASTRIDE];    // 33024 B
    __nv_bfloat16 Al[BM * ASTRIDE];    // 33024 B
    float zsn[NDS];                    // 1 KB
    float2 red[BM][2];                 // (ssq, dot) per row per n-half
    float esum[BM];
};

extern __shared__ char smem_raw[];

__global__ void __launch_bounds__(256, 1)
k_gemm_mma(const float* __restrict__ A, float* __restrict__ out) {
    SmemG& S = *reinterpret_cast<SmemG*>(smem_raw);
    const int tid  = threadIdx.x;
    const int wid  = tid >> 5;
    const int lane = tid & 31;
    const int m0   = blockIdx.x * BM;

    S.zsn[tid] = g_zsn[tid];

    // ---- stage B chunk 0 (16 KB, 64B per thread) ----
    const uint32_t bs0 = smem_u32(&S.Bs[0][0]);
    const uint32_t bs1 = smem_u32(&S.Bs[1][0]);
    const char* gB = reinterpret_cast<const char*>(g_Bf);
#pragma unroll
    for (int j = 0; j < 4; j++)
        cp16(bs0 + tid * 64 + j * 16, gB + tid * 64 + j * 16);
    CP_COMMIT();

    // ---- load A rows, split to bf16 hi/lo in smem (conflict-free layout) ----
    {
        int r = tid >> 2;
        int c4 = (tid & 3) * 2;
        const float* arow = A + (size_t)(m0 + r) * NDA;
        __nv_bfloat16* ah = &S.Ah[r * ASTRIDE];
        __nv_bfloat16* al = &S.Al[r * ASTRIDE];
#pragma unroll
        for (int i = 0; i < 32; i++) {
            int c = c4 + 8 * i;
            float2 v = *reinterpret_cast<const float2*>(arow + c);
            __nv_bfloat16 h0 = __float2bfloat16_rn(v.x);
            __nv_bfloat16 h1 = __float2bfloat16_rn(v.y);
            uint32_t hh = ((uint32_t)__bfloat16_as_ushort(h1) << 16) |
                          __bfloat16_as_ushort(h0);
            uint32_t ll = pack_bf2(v.x - __bfloat162float(h0),
                                   v.y - __bfloat162float(h1));
            *reinterpret_cast<uint32_t*>(ah + c) = hh;
            *reinterpret_cast<uint32_t*>(al + c) = ll;
        }
    }

    float acc[16][4];
#pragma unroll
    for (int j = 0; j < 16; j++)
#pragma unroll
        for (int q = 0; q < 4; q++) acc[j][q] = 0.0f;

    const int mbase = (wid & 3) * 16;
    const int nhalf = wid >> 2;
    const int mlo   = mbase + (lane >> 2);
    const int koff  = (lane & 3) * 2;

    for (int kt = 0; kt < NKT; kt++) {
        const int buf = kt & 1;
        if (kt + 1 < NKT) {
            const uint32_t bsn = buf ? bs0 : bs1;
            const char* src = gB + (size_t)(kt + 1) * 16384;
#pragma unroll
            for (int j = 0; j < 4; j++)
                cp16(bsn + tid * 64 + j * 16, src + tid * 64 + j * 16);
            CP_COMMIT();
            asm volatile("cp.async.wait_group 1;" ::: "memory");
        } else {
            asm volatile("cp.async.wait_group 0;" ::: "memory");
        }
        __syncthreads();

        // A fragments for this k-step (hi and lo)
        const int k0 = kt * 16 + koff;
        uint32_t ah[4], al[4];
        ah[0] = *reinterpret_cast<const uint32_t*>(&S.Ah[mlo * ASTRIDE + k0]);
        ah[1] = *reinterpret_cast<const uint32_t*>(&S.Ah[(mlo + 8) * ASTRIDE + k0]);
        ah[2] = *reinterpret_cast<const uint32_t*>(&S.Ah[mlo * ASTRIDE + k0 + 8]);
        ah[3] = *reinterpret_cast<const uint32_t*>(&S.Ah[(mlo + 8) * ASTRIDE + k0 + 8]);
        al[0] = *reinterpret_cast<const uint32_t*>(&S.Al[mlo * ASTRIDE + k0]);
        al[1] = *reinterpret_cast<const uint32_t*>(&S.Al[(mlo + 8) * ASTRIDE + k0]);
        al[2] = *reinterpret_cast<const uint32_t*>(&S.Al[mlo * ASTRIDE + k0 + 8]);
        al[3] = *reinterpret_cast<const uint32_t*>(&S.Al[(mlo + 8) * ASTRIDE + k0 + 8]);

        const uint2* Bh = &S.Bs[buf][(0 * 32 + nhalf * 16) * 32 + lane];
        const uint2* Bl = &S.Bs[buf][(1 * 32 + nhalf * 16) * 32 + lane];
#pragma unroll
        for (int j = 0; j < 16; j++) {
            uint2 bh = Bh[j * 32];
            uint2 bl = Bl[j * 32];
            MMA_BF16(acc[j], ah, bh.x, bh.y);   // Ah * Bh
            MMA_BF16(acc[j], al, bh.x, bh.y);   // Al * Bh
            MMA_BF16(acc[j], ah, bl.x, bl.y);   // Ah * Bl
        }
        __syncthreads();   // protect buf^1 before next-iter cp.async overwrite
    }

    // ---- epilogue: per-row sumsq & dot(zsn) ----
    // acc[j][0,1] -> row mlo, cols nhalf*128 + j*8 + koff + {0,1}
    // acc[j][2,3] -> row mlo+8, same cols
    float ssq_lo = 0.f, dot_lo = 0.f, ssq_hi = 0.f, dot_hi = 0.f;
#pragma unroll
    for (int j = 0; j < 16; j++) {
        int col = nhalf * 128 + j * 8 + koff;
        float2 z = *reinterpret_cast<const float2*>(&S.zsn[col]);
        ssq_lo += acc[j][0] * acc[j][0] + acc[j][1] * acc[j][1];
        dot_lo += acc[j][0] * z.x + acc[j][1] * z.y;
        ssq_hi += acc[j][2] * acc[j][2] + acc[j][3] * acc[j][3];
        dot_hi += acc[j][2] * z.x + acc[j][3] * z.y;
    }
#pragma unroll
    for (int off = 1; off <= 2; off <<= 1) {
        ssq_lo += __shfl_xor_sync(0xFFFFFFFFu, ssq_lo, off);
        dot_lo += __shfl_xor_sync(0xFFFFFFFFu, dot_lo, off);
        ssq_hi += __shfl_xor_sync(0xFFFFFFFFu, ssq_hi, off);
        dot_hi += __shfl_xor_sync(0xFFFFFFFFu, dot_hi, off);
    }
    if ((lane & 3) == 0) {
        S.red[mlo][nhalf]     = make_float2(ssq_lo, dot_lo);
        S.red[mlo + 8][nhalf] = make_float2(ssq_hi, dot_hi);
    }
    __syncthreads();
    if (tid < BM) {
        float ssq = S.red[tid][0].x + S.red[tid][1].x;
        float dot = S.red[tid][0].y + S.red[tid][1].y;
        float e = dot / fmaxf(sqrtf(ssq), 1e-12f);
        out[OFF_E + m0 + tid] = e;
        S.esum[tid] = e;
    }
    __syncthreads();
    if (tid == 0) {
        double s = 0.0;
        for (int i = 0; i < BM; i++) s += (double)S.esum[i];
        g_part[blockIdx.x] = s;
    }
}

// ============================================================
// Kernel C: starts / ends from e
// ============================================================
__global__ void k_intervals(const float* __restrict__ out_ro, float* __restrict__ out) {
    int m = blockIdx.x * blockDim.x + threadIdx.x;
    if (m >= M_TOTAL) return;
    int v = m >> 13;
    int t = m & (NT - 1);
    float r = g_rview[v];
    const float* e = out_ro + OFF_E;
    bool I  = e[m] >= r;
    bool Ip = (t > 0)      ? (e[m - 1] >= r) : false;
    bool In = (t < NT - 1) ? (e[m + 1] >= r) : false;
    out[OFF_ST + m] = (I && !Ip) ? 1.0f : 0.0f;
    out[OFF_EN + m] = (I && !In) ? 1.0f : 0.0f;
}

// ============================================================
// Kernel D: E_view, I_view, flag_unknown
// ============================================================
__global__ void k_final(float* __restrict__ out) {
    int t = threadIdx.x;  // 64 threads
    double s = 0.0;
    const int per_view = NT / BM;  // 128
    for (int i = 0; i < per_view; i++) s += g_part[t * per_view + i];
    float ev = (float)(s / (double)NT);
    out[OFF_EV + t] = ev;
    bool iv = ev >= g_rview[t];
    out[OFF_IV + t] = iv ? 1.0f : 0.0f;
    int any = __syncthreads_or(iv ? 1 : 0);
    if (t == 0)
        out[OFF_FLAG] = ((out[OFF_PDET] >= 0.5f) && !any) ? 1.0f : 0.0f;
}

// ============================================================
extern "C" void kernel_launch(void* const* d_in, const int* in_sizes, int n_in,
                              void* d_out, int out_size) {
    const float* h      = (const float*)d_in[0];
    const float* alpha  = (const float*)d_in[1];
    const float* pi     = (const float*)d_in[2];
    const float* US     = (const float*)d_in[3];
    const float* Ws_w   = (const float*)d_in[6];
    const float* Ws_b   = (const float*)d_in[7];
    const float* det_w  = (const float*)d_in[8];
    const float* det_b  = (const float*)d_in[9];
    const float* cls_w  = (const float*)d_in[10];
    const float* cls_b  = (const float*)d_in[11];
    const float* Wwin   = (const float*)d_in[12];
    const float* tau_c0 = (const float*)d_in[13];
    const float* lamU   = (const float*)d_in[14];
    const float* lamC   = (const float*)d_in[15];
    const float* lamP   = (const float*)d_in[16];
    const float* lamPi  = (const float*)d_in[17];
    const float* nu     = (const float*)d_in[18];
    const float* risk   = (const float*)d_in[19];
    float* out = (float*)d_out;

    static bool attr_set = false;
    if (!attr_set) {
        cudaFuncSetAttribute(k_gemm_mma, cudaFuncAttributeMaxDynamicSharedMemorySize,
                             (int)sizeof(SmemG));
        attr_set = true;
    }

    k_prep_b<<<64, 256>>>(Wwin);
    k_scalars<<<1, 256>>>(alpha, pi, US, Ws_w, Ws_b, det_w, det_b, cls_w, cls_b,
                          tau_c0, lamU, lamC, lamP, lamPi, nu, risk, out);
    k_gemm_mma<<<GEMM_BLOCKS, 256, sizeof(SmemG)>>>(h, out);
    k_intervals<<<(M_TOTAL + 255) / 256, 256>>>(out, out);
    k_final<<<1, NV>>>(out);
}

// round 12
// speedup vs baseline: 1.7906x; 1.7906x over previous
#include <cuda_runtime.h>
#include <cuda_bf16.h>
#include <cstdint>

// Problem dims
#define NV 64
#define NT 8192
#define NDA 256
#define NDS 256
#define NKR 8
#define NDU 64
#define NKA 40
#define M_TOTAL (NV * NT)  // 524288

// Output layout (float32, tuple flattened in reference-return order)
#define OFF_PDET 0
#define OFF_TAUX 1
#define OFF_YHAT 2
#define OFF_E    42
#define OFF_EV   (OFF_E + M_TOTAL)
#define OFF_RV   (OFF_EV + NV)
#define OFF_IV   (OFF_RV + NV)
#define OFF_ST   (OFF_IV + NV)
#define OFF_EN   (OFF_ST + M_TOTAL)
#define OFF_FLAG (OFF_EN + M_TOTAL)

// GEMM tiling: CTA = 64 rows x 256 cols, k-steps of 16
#define BM 64
#define NKT 16                       // 256 / 16
#define GEMM_BLOCKS (M_TOTAL / BM)   // 8192
#define APACK_STRIDE 132             // uint2 per row (conflict-free LDS.64)

// -------- device scratch --------
// B fragments: [kt(16)][term(2: hi,lo)][ntile(32)][lane(32)] as uint2 (256 KB, L2-resident)
__device__ uint2  g_Bf[NKT * 2 * 32 * 32];
__device__ float  g_zsn[NDS];
__device__ float  g_rview[NV];
__device__ double g_part[GEMM_BLOCKS];

// -------- helpers --------
__device__ __forceinline__ uint32_t pack_bf2(float a, float b) {
    __nv_bfloat162 h = __floats2bfloat162_rn(a, b);
    return *reinterpret_cast<uint32_t*>(&h);
}

#define MMA_BF16(cr, a, bx, by) \
    asm volatile( \
        "mma.sync.aligned.m16n8k16.row.col.f32.bf16.bf16.f32 " \
        "{%0,%1,%2,%3},{%4,%5,%6,%7},{%8,%9},{%0,%1,%2,%3};" \
        : "+f"((cr)[0]), "+f"((cr)[1]), "+f"((cr)[2]), "+f"((cr)[3]) \
        : "r"((a)[0]), "r"((a)[1]), "r"((a)[2]), "r"((a)[3]), "r"(bx), "r"(by))

// ============================================================
// Kernel P: build bf16 hi/lo B fragments in mma.sync per-lane layout
//   B[n][k] = Wwin[n*256 + k]; frag (kt, nt, lane):
//   n = nt*8 + lane/4, k0 = kt*16 + (lane%4)*2
//   reg.x = {B[k0], B[k0+1]}, reg.y = {B[k0+8], B[k0+9]}
// ============================================================
__global__ void k_prep_b(const float* __restrict__ W) {
    int t = blockIdx.x * 256 + threadIdx.x;   // 16384 total
    int kt = t >> 10, nt = (t >> 5) & 31, lane = t & 31;
    int n  = nt * 8 + (lane >> 2);
    int k0 = kt * 16 + (lane & 3) * 2;
    const float* row = W + n * NDA;
    float v0 = row[k0], v1 = row[k0 + 1], v2 = row[k0 + 8], v3 = row[k0 + 9];
    __nv_bfloat16 h0 = __float2bfloat16_rn(v0), h1 = __float2bfloat16_rn(v1);
    __nv_bfloat16 h2 = __float2bfloat16_rn(v2), h3 = __float2bfloat16_rn(v3);
    uint2 hv, lv;
    hv.x = ((uint32_t)__bfloat16_as_ushort(h1) << 16) | __bfloat16_as_ushort(h0);
    hv.y = ((uint32_t)__bfloat16_as_ushort(h3) << 16) | __bfloat16_as_ushort(h2);
    lv.x = pack_bf2(v0 - __bfloat162float(h0), v1 - __bfloat162float(h1));
    lv.y = pack_bf2(v2 - __bfloat162float(h2), v3 - __bfloat162float(h3));
    g_Bf[((kt * 2 + 0) * 32 + nt) * 32 + lane] = hv;
    g_Bf[((kt * 2 + 1) * 32 + nt) * 32 + lane] = lv;
}

// ============================================================
// Kernel A: scalars — zs, s, tau_x, p_det, y_hat, r_view, zsn
// ============================================================
__global__ void k_scalars(const float* __restrict__ alpha, const float* __restrict__ pi,
                          const float* __restrict__ US,
                          const float* __restrict__ Ws_w, const float* __restrict__ Ws_b,
                          const float* __restrict__ det_w, const float* __restrict__ det_b,
                          const float* __restrict__ cls_w, const float* __restrict__ cls_b,
                          const float* __restrict__ tau_c0, const float* __restrict__ lamU,
                          const float* __restrict__ lamC, const float* __restrict__ lamP,
                          const float* __restrict__ lamPi, const float* __restrict__ nu,
                          const float* __restrict__ risk, float* __restrict__ out) {
    __shared__ float us[NKR * NDU];
    __shared__ float zs[NDS];
    __shared__ float red[256];
    int t = threadIdx.x;
    us[t] = US[t];
    us[t + 256] = US[t + 256];
    __syncthreads();

    float z = Ws_b[t];
#pragma unroll 4
    for (int k = 0; k < NKR * NDU; k++) z += Ws_w[t * (NKR * NDU) + k] * us[k];
    zs[t] = z;
    __syncthreads();

    red[t] = z * z;
    __syncthreads();
    for (int s = 128; s > 0; s >>= 1) { if (t < s) red[t] += red[t + s]; __syncthreads(); }
    float ss = red[0];
    __syncthreads();

    red[t] = z * det_w[t];
    __syncthreads();
    for (int s = 128; s > 0; s >>= 1) { if (t < s) red[t] += red[t + s]; __syncthreads(); }
    float sdet = red[0] + det_b[0];
    __syncthreads();

    float norm = fmaxf(sqrtf(ss), 1e-12f);
    g_zsn[t] = zs[t] / norm;

    if (t < NKA) {
        float y = cls_b[t];
#pragma unroll 4
        for (int j = 0; j < NDS; j++) y += cls_w[t * NDS + j] * zs[j];
        out[OFF_YHAT + t] = 1.0f / (1.0f + expf(-y));
    }
    if (t < NV) {
        float r = -0.5f * alpha[t];
        g_rview[t] = r;
        out[OFF_RV + t] = r;
    }
    if (t == 0) {
        float ha = 0.0f;
        for (int i = 0; i < NV; i++) { float a = alpha[i]; ha += a * logf(a + 1e-8f); }
        float Ca = 1.0f - (-ha) / logf((float)NV);
        float hp = 0.0f;
        for (int i = 0; i < NKR; i++) { float p = pi[i]; hp += p * logf(p + 1e-8f); }
        float up = (-hp) / logf((float)NKR);
        float tx = tau_c0[0] - lamU[0] * nu[0] - lamC[0] * Ca + lamP[0] * risk[0] + lamPi[0] * up;
        out[OFF_TAUX] = tx;
        out[OFF_PDET] = 1.0f / (1.0f + expf(-(sdet - tx)));
    }
}

// ============================================================
// Kernel B: bf16 mma.sync GEMM (3-term hi/lo split) + fused row reduce -> e
//   Barrier-free mainloop: A hi/lo packed in smem (uint2), B fragments LDG'd
//   straight from L2-resident g_Bf. 8 warps: mtile = wid&3, nhalf = wid>>2.
// ============================================================
struct __align__(16) SmemG {
    uint2 Apack[BM * APACK_STRIDE];    // {hi2, lo2} per k-pair, 67584 B
    float zsn[NDS];                    // 1 KB
    float2 red[BM][2];                 // (ssq, dot) per row per n-half
    float esum[BM];
};

extern __shared__ char smem_raw[];

__global__ void __launch_bounds__(256, 2)
k_gemm_mma(const float* __restrict__ A, float* __restrict__ out) {
    SmemG& S = *reinterpret_cast<SmemG*>(smem_raw);
    const int tid  = threadIdx.x;
    const int wid  = tid >> 5;
    const int lane = tid & 31;
    const int m0   = blockIdx.x * BM;

    S.zsn[tid] = g_zsn[tid];

    // ---- load A rows, split to bf16 hi/lo, pack interleaved ----
    // thread: row r = tid>>2, k-pairs p = (tid&3) + 4*i, i = 0..31
    {
        int r = tid >> 2;
        int pbase = tid & 3;
        const float* arow = A + (size_t)(m0 + r) * NDA;
        uint2* ap = &S.Apack[r * APACK_STRIDE];
#pragma unroll
        for (int i = 0; i < 32; i++) {
            int p = pbase + 4 * i;
            float2 v = *reinterpret_cast<const float2*>(arow + 2 * p);
            __nv_bfloat16 h0 = __float2bfloat16_rn(v.x);
            __nv_bfloat16 h1 = __float2bfloat16_rn(v.y);
            uint2 w;
            w.x = ((uint32_t)__bfloat16_as_ushort(h1) << 16) |
                  __bfloat16_as_ushort(h0);
            w.y = pack_bf2(v.x - __bfloat162float(h0),
                           v.y - __bfloat162float(h1));
            ap[p] = w;
        }
    }
    __syncthreads();   // the only barrier before the epilogue

    float acc[16][4];
#pragma unroll
    for (int j = 0; j < 16; j++)
#pragma unroll
        for (int q = 0; q < 4; q++) acc[j][q] = 0.0f;

    const int mbase = (wid & 3) * 16;
    const int nhalf = wid >> 2;
    const int mlo   = mbase + (lane >> 2);
    const int koff  = (lane & 3) * 2;

    for (int kt = 0; kt < NKT; kt++) {
        // A fragments: p0 = kt*8 + (lane&3); rows mlo, mlo+8; pairs p0, p0+4
        const int p0 = kt * 8 + (lane & 3);
        uint2 a00 = S.Apack[mlo * APACK_STRIDE + p0];
        uint2 a10 = S.Apack[(mlo + 8) * APACK_STRIDE + p0];
        uint2 a01 = S.Apack[mlo * APACK_STRIDE + p0 + 4];
        uint2 a11 = S.Apack[(mlo + 8) * APACK_STRIDE + p0 + 4];
        uint32_t ah[4] = { a00.x, a10.x, a01.x, a11.x };
        uint32_t al[4] = { a00.y, a10.y, a01.y, a11.y };

        const uint2* Bh = &g_Bf[((kt * 2 + 0) * 32 + nhalf * 16) * 32 + lane];
        const uint2* Bl = &g_Bf[((kt * 2 + 1) * 32 + nhalf * 16) * 32 + lane];

#pragma unroll
        for (int half = 0; half < 2; half++) {
            uint2 bh[8], bl[8];
#pragma unroll
            for (int j = 0; j < 8; j++) {
                bh[j] = Bh[(half * 8 + j) * 32];
                bl[j] = Bl[(half * 8 + j) * 32];
            }
#pragma unroll
            for (int j = 0; j < 8; j++) {
                float* cr = acc[half * 8 + j];
                MMA_BF16(cr, ah, bh[j].x, bh[j].y);   // Ah * Bh
                MMA_BF16(cr, al, bh[j].x, bh[j].y);   // Al * Bh
                MMA_BF16(cr, ah, bl[j].x, bl[j].y);   // Ah * Bl
            }
        }
    }

    // ---- epilogue: per-row sumsq & dot(zsn) ----
    // acc[j][0,1] -> row mlo, cols nhalf*128 + j*8 + koff + {0,1}
    // acc[j][2,3] -> row mlo+8, same cols
    float ssq_lo = 0.f, dot_lo = 0.f, ssq_hi = 0.f, dot_hi = 0.f;
#pragma unroll
    for (int j = 0; j < 16; j++) {
        int col = nhalf * 128 + j * 8 + koff;
        float2 z = *reinterpret_cast<const float2*>(&S.zsn[col]);
        ssq_lo += acc[j][0] * acc[j][0] + acc[j][1] * acc[j][1];
        dot_lo += acc[j][0] * z.x + acc[j][1] * z.y;
        ssq_hi += acc[j][2] * acc[j][2] + acc[j][3] * acc[j][3];
        dot_hi += acc[j][2] * z.x + acc[j][3] * z.y;
    }
#pragma unroll
    for (int off = 1; off <= 2; off <<= 1) {
        ssq_lo += __shfl_xor_sync(0xFFFFFFFFu, ssq_lo, off);
        dot_lo += __shfl_xor_sync(0xFFFFFFFFu, dot_lo, off);
        ssq_hi += __shfl_xor_sync(0xFFFFFFFFu, ssq_hi, off);
        dot_hi += __shfl_xor_sync(0xFFFFFFFFu, dot_hi, off);
    }
    if ((lane & 3) == 0) {
        S.red[mlo][nhalf]     = make_float2(ssq_lo, dot_lo);
        S.red[mlo + 8][nhalf] = make_float2(ssq_hi, dot_hi);
    }
    __syncthreads();
    if (tid < BM) {
        float ssq = S.red[tid][0].x + S.red[tid][1].x;
        float dot = S.red[tid][0].y + S.red[tid][1].y;
        float e = dot / fmaxf(sqrtf(ssq), 1e-12f);
        out[OFF_E + m0 + tid] = e;
        S.esum[tid] = e;
    }
    __syncthreads();
    if (tid == 0) {
        double s = 0.0;
        for (int i = 0; i < BM; i++) s += (double)S.esum[i];
        g_part[blockIdx.x] = s;
    }
}

// ============================================================
// Kernel C: starts / ends from e
// ============================================================
__global__ void k_intervals(const float* __restrict__ out_ro, float* __restrict__ out) {
    int m = blockIdx.x * blockDim.x + threadIdx.x;
    if (m >= M_TOTAL) return;
    int v = m >> 13;
    int t = m & (NT - 1);
    float r = g_rview[v];
    const float* e = out_ro + OFF_E;
    bool I  = e[m] >= r;
    bool Ip = (t > 0)      ? (e[m - 1] >= r) : false;
    bool In = (t < NT - 1) ? (e[m + 1] >= r) : false;
    out[OFF_ST + m] = (I && !Ip) ? 1.0f : 0.0f;
    out[OFF_EN + m] = (I && !In) ? 1.0f : 0.0f;
}

// ============================================================
// Kernel D: E_view, I_view, flag_unknown
// ============================================================
__global__ void k_final(float* __restrict__ out) {
    int t = threadIdx.x;  // 64 threads
    double s = 0.0;
    const int per_view = NT / BM;  // 128
    for (int i = 0; i < per_view; i++) s += g_part[t * per_view + i];
    float ev = (float)(s / (double)NT);
    out[OFF_EV + t] = ev;
    bool iv = ev >= g_rview[t];
    out[OFF_IV + t] = iv ? 1.0f : 0.0f;
    int any = __syncthreads_or(iv ? 1 : 0);
    if (t == 0)
        out[OFF_FLAG] = ((out[OFF_PDET] >= 0.5f) && !any) ? 1.0f : 0.0f;
}

// ============================================================
extern "C" void kernel_launch(void* const* d_in, const int* in_sizes, int n_in,
                              void* d_out, int out_size) {
    const float* h      = (const float*)d_in[0];
    const float* alpha  = (const float*)d_in[1];
    const float* pi     = (const float*)d_in[2];
    const float* US     = (const float*)d_in[3];
    const float* Ws_w   = (const float*)d_in[6];
    const float* Ws_b   = (const float*)d_in[7];
    const float* det_w  = (const float*)d_in[8];
    const float* det_b  = (const float*)d_in[9];
    const float* cls_w  = (const float*)d_in[10];
    const float* cls_b  = (const float*)d_in[11];
    const float* Wwin   = (const float*)d_in[12];
    const float* tau_c0 = (const float*)d_in[13];
    const float* lamU   = (const float*)d_in[14];
    const float* lamC   = (const float*)d_in[15];
    const float* lamP   = (const float*)d_in[16];
    const float* lamPi  = (const float*)d_in[17];
    const float* nu     = (const float*)d_in[18];
    const float* risk   = (const float*)d_in[19];
    float* out = (float*)d_out;

    static bool attr_set = false;
    if (!attr_set) {
        cudaFuncSetAttribute(k_gemm_mma, cudaFuncAttributeMaxDynamicSharedMemorySize,
                             (int)sizeof(SmemG));
        attr_set = true;
    }

    k_prep_b<<<64, 256>>>(Wwin);
    k_scalars<<<1, 256>>>(alpha, pi, US, Ws_w, Ws_b, det_w, det_b, cls_w, cls_b,
                          tau_c0, lamU, lamC, lamP, lamPi, nu, risk, out);
    k_gemm_mma<<<GEMM_BLOCKS, 256, sizeof(SmemG)>>>(h, out);
    k_intervals<<<(M_TOTAL + 255) / 256, 256>>>(out, out);
    k_final<<<1, NV>>>(out);
}

// round 16
// speedup vs baseline: 2.0345x; 1.1362x over previous
#include <cuda_runtime.h>
#include <cuda_bf16.h>
#include <cstdint>

// Problem dims
#define NV 64
#define NT 8192
#define NDA 256
#define NDS 256
#define NKR 8
#define NDU 64
#define NKA 40
#define M_TOTAL (NV * NT)  // 524288

// Output layout (float32, tuple flattened in reference-return order)
#define OFF_PDET 0
#define OFF_TAUX 1
#define OFF_YHAT 2
#define OFF_E    42
#define OFF_EV   (OFF_E + M_TOTAL)
#define OFF_RV   (OFF_EV + NV)
#define OFF_IV   (OFF_RV + NV)
#define OFF_ST   (OFF_IV + NV)
#define OFF_EN   (OFF_ST + M_TOTAL)
#define OFF_FLAG (OFF_EN + M_TOTAL)

// GEMM tiling: CTA = 64 rows x 256 cols, k-steps of 16
// 8 warps partitioned by N: warp w owns cols [w*32, w*32+32), all 64 rows.
#define BM 64
#define NKT 16                       // 256 / 16
#define GEMM_BLOCKS (M_TOTAL / BM)   // 8192
#define APACK_STRIDE 132             // uint2 per row (conflict-free-ish LDS.64)

// -------- device scratch --------
// B fragments: [kt(16)][term(2: hi,lo)][ntile(32)][lane(32)] as uint2 (256 KB, L2-resident)
__device__ uint2  g_Bf[NKT * 2 * 32 * 32];
__device__ float  g_zsn[NDS];
__device__ float  g_rview[NV];
__device__ double g_part[GEMM_BLOCKS];

// -------- helpers --------
__device__ __forceinline__ uint32_t pack_bf2(float a, float b) {
    __nv_bfloat162 h = __floats2bfloat162_rn(a, b);
    return *reinterpret_cast<uint32_t*>(&h);
}

#define MMA_BF16(cr, a, bx, by) \
    asm volatile( \
        "mma.sync.aligned.m16n8k16.row.col.f32.bf16.bf16.f32 " \
        "{%0,%1,%2,%3},{%4,%5,%6,%7},{%8,%9},{%0,%1,%2,%3};" \
        : "+f"((cr)[0]), "+f"((cr)[1]), "+f"((cr)[2]), "+f"((cr)[3]) \
        : "r"((a)[0]), "r"((a)[1]), "r"((a)[2]), "r"((a)[3]), "r"(bx), "r"(by))

// ============================================================
// Kernel P: build bf16 hi/lo B fragments in mma.sync per-lane layout
//   B[n][k] = Wwin[n*256 + k]; frag (kt, nt, lane):
//   n = nt*8 + lane/4, k0 = kt*16 + (lane%4)*2
//   reg.x = {B[k0], B[k0+1]}, reg.y = {B[k0+8], B[k0+9]}
// ============================================================
__global__ void k_prep_b(const float* __restrict__ W) {
    int t = blockIdx.x * 256 + threadIdx.x;   // 16384 total
    int kt = t >> 10, nt = (t >> 5) & 31, lane = t & 31;
    int n  = nt * 8 + (lane >> 2);
    int k0 = kt * 16 + (lane & 3) * 2;
    const float* row = W + n * NDA;
    float v0 = row[k0], v1 = row[k0 + 1], v2 = row[k0 + 8], v3 = row[k0 + 9];
    __nv_bfloat16 h0 = __float2bfloat16_rn(v0), h1 = __float2bfloat16_rn(v1);
    __nv_bfloat16 h2 = __float2bfloat16_rn(v2), h3 = __float2bfloat16_rn(v3);
    uint2 hv, lv;
    hv.x = ((uint32_t)__bfloat16_as_ushort(h1) << 16) | __bfloat16_as_ushort(h0);
    hv.y = ((uint32_t)__bfloat16_as_ushort(h3) << 16) | __bfloat16_as_ushort(h2);
    lv.x = pack_bf2(v0 - __bfloat162float(h0), v1 - __bfloat162float(h1));
    lv.y = pack_bf2(v2 - __bfloat162float(h2), v3 - __bfloat162float(h3));
    g_Bf[((kt * 2 + 0) * 32 + nt) * 32 + lane] = hv;
    g_Bf[((kt * 2 + 1) * 32 + nt) * 32 + lane] = lv;
}

// ============================================================
// Kernel A: scalars — zs, s, tau_x, p_det, y_hat, r_view, zsn
// ============================================================
__global__ void k_scalars(const float* __restrict__ alpha, const float* __restrict__ pi,
                          const float* __restrict__ US,
                          const float* __restrict__ Ws_w, const float* __restrict__ Ws_b,
                          const float* __restrict__ det_w, const float* __restrict__ det_b,
                          const float* __restrict__ cls_w, const float* __restrict__ cls_b,
                          const float* __restrict__ tau_c0, const float* __restrict__ lamU,
                          const float* __restrict__ lamC, const float* __restrict__ lamP,
                          const float* __restrict__ lamPi, const float* __restrict__ nu,
                          const float* __restrict__ risk, float* __restrict__ out) {
    __shared__ float us[NKR * NDU];
    __shared__ float zs[NDS];
    __shared__ float red[256];
    int t = threadIdx.x;
    us[t] = US[t];
    us[t + 256] = US[t + 256];
    __syncthreads();

    float z = Ws_b[t];
#pragma unroll 4
    for (int k = 0; k < NKR * NDU; k++) z += Ws_w[t * (NKR * NDU) + k] * us[k];
    zs[t] = z;
    __syncthreads();

    red[t] = z * z;
    __syncthreads();
    for (int s = 128; s > 0; s >>= 1) { if (t < s) red[t] += red[t + s]; __syncthreads(); }
    float ss = red[0];
    __syncthreads();

    red[t] = z * det_w[t];
    __syncthreads();
    for (int s = 128; s > 0; s >>= 1) { if (t < s) red[t] += red[t + s]; __syncthreads(); }
    float sdet = red[0] + det_b[0];
    __syncthreads();

    float norm = fmaxf(sqrtf(ss), 1e-12f);
    g_zsn[t] = zs[t] / norm;

    if (t < NKA) {
        float y = cls_b[t];
#pragma unroll 4
        for (int j = 0; j < NDS; j++) y += cls_w[t * NDS + j] * zs[j];
        out[OFF_YHAT + t] = 1.0f / (1.0f + expf(-y));
    }
    if (t < NV) {
        float r = -0.5f * alpha[t];
        g_rview[t] = r;
        out[OFF_RV + t] = r;
    }
    if (t == 0) {
        float ha = 0.0f;
        for (int i = 0; i < NV; i++) { float a = alpha[i]; ha += a * logf(a + 1e-8f); }
        float Ca = 1.0f - (-ha) / logf((float)NV);
        float hp = 0.0f;
        for (int i = 0; i < NKR; i++) { float p = pi[i]; hp += p * logf(p + 1e-8f); }
        float up = (-hp) / logf((float)NKR);
        float tx = tau_c0[0] - lamU[0] * nu[0] - lamC[0] * Ca + lamP[0] * risk[0] + lamPi[0] * up;
        out[OFF_TAUX] = tx;
        out[OFF_PDET] = 1.0f / (1.0f + expf(-(sdet - tx)));
    }
}

// ============================================================
// Kernel B: bf16 mma.sync GEMM (3-term hi/lo split) + fused row reduce -> e
//   Warps partitioned by N (disjoint B reads -> 4x less L2 traffic):
//   warp w: ntiles 4w..4w+3 (cols w*32..w*32+31), all 4 m-tiles.
// ============================================================
struct __align__(16) SmemG {
    uint2 Apack[BM * APACK_STRIDE];    // {hi2, lo2} per k-pair, 67584 B
    float zsn[NDS];                    // 1 KB
    float2 red[BM][8];                 // (ssq, dot) per row per warp
    float esum[BM];
};

extern __shared__ char smem_raw[];

__global__ void __launch_bounds__(256, 2)
k_gemm_mma(const float* __restrict__ A, float* __restrict__ out) {
    SmemG& S = *reinterpret_cast<SmemG*>(smem_raw);
    const int tid  = threadIdx.x;
    const int wid  = tid >> 5;
    const int lane = tid & 31;
    const int m0   = blockIdx.x * BM;

    S.zsn[tid] = g_zsn[tid];

    // ---- load A rows, split to bf16 hi/lo, pack interleaved ----
    // thread: row r = tid>>2, k-pairs p = (tid&3) + 4*i, i = 0..31
    {
        int r = tid >> 2;
        int pbase = tid & 3;
        const float* arow = A + (size_t)(m0 + r) * NDA;
        uint2* ap = &S.Apack[r * APACK_STRIDE];
#pragma unroll
        for (int i = 0; i < 32; i++) {
            int p = pbase + 4 * i;
            float2 v = *reinterpret_cast<const float2*>(arow + 2 * p);
            __nv_bfloat16 h0 = __float2bfloat16_rn(v.x);
            __nv_bfloat16 h1 = __float2bfloat16_rn(v.y);
            uint2 w;
            w.x = ((uint32_t)__bfloat16_as_ushort(h1) << 16) |
                  __bfloat16_as_ushort(h0);
            w.y = pack_bf2(v.x - __bfloat162float(h0),
                           v.y - __bfloat162float(h1));
            ap[p] = w;
        }
    }
    __syncthreads();   // the only barrier before the epilogue

    float acc[4][4][4];   // [mtile][ntile][quad]
#pragma unroll
    for (int mt = 0; mt < 4; mt++)
#pragma unroll
        for (int nt = 0; nt < 4; nt++)
#pragma unroll
            for (int q = 0; q < 4; q++) acc[mt][nt][q] = 0.0f;

    const int rsub = lane >> 2;        // 0..7 row-within-mtile
    const int koff = (lane & 3) * 2;

    for (int kt = 0; kt < NKT; kt++) {
        // B fragments: warp's 4 ntiles, hi+lo (disjoint across warps)
        const uint2* Bh = &g_Bf[((kt * 2 + 0) * 32 + wid * 4) * 32 + lane];
        const uint2* Bl = &g_Bf[((kt * 2 + 1) * 32 + wid * 4) * 32 + lane];
        uint2 bh[4], bl[4];
#pragma unroll
        for (int nt = 0; nt < 4; nt++) {
            bh[nt] = Bh[nt * 32];
            bl[nt] = Bl[nt * 32];
        }
        const int p0 = kt * 8 + (lane & 3);
#pragma unroll
        for (int mt = 0; mt < 4; mt++) {
            const uint2* ap_lo = &S.Apack[(mt * 16 + rsub) * APACK_STRIDE];
            const uint2* ap_hi = ap_lo + 8 * APACK_STRIDE;
            uint2 a00 = ap_lo[p0];
            uint2 a10 = ap_hi[p0];
            uint2 a01 = ap_lo[p0 + 4];
            uint2 a11 = ap_hi[p0 + 4];
            uint32_t ah[4] = { a00.x, a10.x, a01.x, a11.x };
            uint32_t al[4] = { a00.y, a10.y, a01.y, a11.y };
#pragma unroll
            for (int nt = 0; nt < 4; nt++) {
                float* cr = acc[mt][nt];
                MMA_BF16(cr, ah, bh[nt].x, bh[nt].y);   // Ah * Bh
                MMA_BF16(cr, al, bh[nt].x, bh[nt].y);   // Al * Bh
                MMA_BF16(cr, ah, bl[nt].x, bl[nt].y);   // Ah * Bl
            }
        }
    }

    // ---- epilogue: per-row sumsq & dot(zsn) over this warp's 32 cols ----
    // acc[mt][nt][0,1] -> row mt*16+rsub,   col wid*32 + nt*8 + koff + {0,1}
    // acc[mt][nt][2,3] -> row mt*16+rsub+8, same cols
#pragma unroll
    for (int mt = 0; mt < 4; mt++) {
        float ssq_lo = 0.f, dot_lo = 0.f, ssq_hi = 0.f, dot_hi = 0.f;
#pragma unroll
        for (int nt = 0; nt < 4; nt++) {
            int col = wid * 32 + nt * 8 + koff;
            float2 z = *reinterpret_cast<const float2*>(&S.zsn[col]);
            float* cr = acc[mt][nt];
            ssq_lo += cr[0] * cr[0] + cr[1] * cr[1];
            dot_lo += cr[0] * z.x + cr[1] * z.y;
            ssq_hi += cr[2] * cr[2] + cr[3] * cr[3];
            dot_hi += cr[2] * z.x + cr[3] * z.y;
        }
#pragma unroll
        for (int off = 1; off <= 2; off <<= 1) {
            ssq_lo += __shfl_xor_sync(0xFFFFFFFFu, ssq_lo, off);
            dot_lo += __shfl_xor_sync(0xFFFFFFFFu, dot_lo, off);
            ssq_hi += __shfl_xor_sync(0xFFFFFFFFu, ssq_hi, off);
            dot_hi += __shfl_xor_sync(0xFFFFFFFFu, dot_hi, off);
        }
        if ((lane & 3) == 0) {
            S.red[mt * 16 + rsub][wid]     = make_float2(ssq_lo, dot_lo);
            S.red[mt * 16 + rsub + 8][wid] = make_float2(ssq_hi, dot_hi);
        }
    }
    __syncthreads();
    if (tid < BM) {
        float ssq = 0.f, dot = 0.f;
#pragma unroll
        for (int w = 0; w < 8; w++) {
            float2 rd = S.red[tid][w];
            ssq += rd.x;
            dot += rd.y;
        }
        float e = dot / fmaxf(sqrtf(ssq), 1e-12f);
        out[OFF_E + m0 + tid] = e;
        S.esum[tid] = e;
    }
    __syncthreads();
    if (tid == 0) {
        double s = 0.0;
        for (int i = 0; i < BM; i++) s += (double)S.esum[i];
        g_part[blockIdx.x] = s;
    }
}

// ============================================================
// Kernel C: starts / ends from e
// ============================================================
__global__ void k_intervals(const float* __restrict__ out_ro, float* __restrict__ out) {
    int m = blockIdx.x * blockDim.x + threadIdx.x;
    if (m >= M_TOTAL) return;
    int v = m >> 13;
    int t = m & (NT - 1);
    float r = g_rview[v];
    const float* e = out_ro + OFF_E;
    bool I  = e[m] >= r;
    bool Ip = (t > 0)      ? (e[m - 1] >= r) : false;
    bool In = (t < NT - 1) ? (e[m + 1] >= r) : false;
    out[OFF_ST + m] = (I && !Ip) ? 1.0f : 0.0f;
    out[OFF_EN + m] = (I && !In) ? 1.0f : 0.0f;
}

// ============================================================
// Kernel D: E_view, I_view, flag_unknown
// ============================================================
__global__ void k_final(float* __restrict__ out) {
    int t = threadIdx.x;  // 64 threads
    double s = 0.0;
    const int per_view = NT / BM;  // 128
    for (int i = 0; i < per_view; i++) s += g_part[t * per_view + i];
    float ev = (float)(s / (double)NT);
    out[OFF_EV + t] = ev;
    bool iv = ev >= g_rview[t];
    out[OFF_IV + t] = iv ? 1.0f : 0.0f;
    int any = __syncthreads_or(iv ? 1 : 0);
    if (t == 0)
        out[OFF_FLAG] = ((out[OFF_PDET] >= 0.5f) && !any) ? 1.0f : 0.0f;
}

// ============================================================
extern "C" void kernel_launch(void* const* d_in, const int* in_sizes, int n_in,
                              void* d_out, int out_size) {
    const float* h      = (const float*)d_in[0];
    const float* alpha  = (const float*)d_in[1];
    const float* pi     = (const float*)d_in[2];
    const float* US     = (const float*)d_in[3];
    const float* Ws_w   = (const float*)d_in[6];
    const float* Ws_b   = (const float*)d_in[7];
    const float* det_w  = (const float*)d_in[8];
    const float* det_b  = (const float*)d_in[9];
    const float* cls_w  = (const float*)d_in[10];
    const float* cls_b  = (const float*)d_in[11];
    const float* Wwin   = (const float*)d_in[12];
    const float* tau_c0 = (const float*)d_in[13];
    const float* lamU   = (const float*)d_in[14];
    const float* lamC   = (const float*)d_in[15];
    const float* lamP   = (const float*)d_in[16];
    const float* lamPi  = (const float*)d_in[17];
    const float* nu     = (const float*)d_in[18];
    const float* risk   = (const float*)d_in[19];
    float* out = (float*)d_out;

    static bool attr_set = false;
    if (!attr_set) {
        cudaFuncSetAttribute(k_gemm_mma, cudaFuncAttributeMaxDynamicSharedMemorySize,
                             (int)sizeof(SmemG));
        attr_set = true;
    }

    k_prep_b<<<64, 256>>>(Wwin);
    k_scalars<<<1, 256>>>(alpha, pi, US, Ws_w, Ws_b, det_w, det_b, cls_w, cls_b,
                          tau_c0, lamU, lamC, lamP, lamPi, nu, risk, out);
    k_gemm_mma<<<GEMM_BLOCKS, 256, sizeof(SmemG)>>>(h, out);
    k_intervals<<<(M_TOTAL + 255) / 256, 256>>>(out, out);
    k_final<<<1, NV>>>(out);
}